// round 1
// baseline (speedup 1.0000x reference)
#include <cuda_runtime.h>
#include <cstdint>

#define BB 16
#define LL 1024
#define HH 768

// Scratch (allocation-guard-safe device globals)
__device__ float g_xproj[BB * LL * HH];        // 48 MB
__device__ float g_yproj[BB * LL * HH];        // 48 MB
__device__ float g_scores[(size_t)BB * LL * LL]; // 64 MB
__device__ int   g_x2mask[BB * LL];

// ---------------------------------------------------------------------------
// Mask dtype detection + normalization.
// uint8(bool): random 0/1 bytes everywhere.
// int32: bytes at (i%4)!=0 are all zero.
// float32 (0.0/1.0): bytes at (i%4)==0 are all zero (1.0f = 00 00 80 3F).
// ---------------------------------------------------------------------------
__global__ void mask_convert_kernel(const unsigned char* __restrict__ m, int n) {
    __shared__ int s0_sh, s123_sh;
    int tid = threadIdx.x;
    if (tid == 0) { s0_sh = 0; s123_sh = 0; }
    __syncthreads();
    int o0 = 0, o123 = 0;
    for (int i = tid; i < n; i += blockDim.x) {
        unsigned char v = m[i];
        if ((i & 3) == 0) o0 |= v; else o123 |= v;
    }
    atomicOr(&s0_sh, o0);
    atomicOr(&s123_sh, o123);
    __syncthreads();
    int mode; // 0 = uint8, 1 = int32, 2 = float32
    if (s123_sh == 0)      mode = 1;
    else if (s0_sh == 0)   mode = 2;
    else                   mode = 0;
    for (int j = tid; j < n; j += blockDim.x) {
        int v;
        if (mode == 1)      v = (m[4 * j] != 0);
        else if (mode == 2) v = ((m[4 * j + 1] | m[4 * j + 2] | m[4 * j + 3]) != 0);
        else                v = (m[j] != 0);
        g_x2mask[j] = v;
    }
}

// ---------------------------------------------------------------------------
// GEMM  C[M,N] = A[M,K] * B[N,K]^T   (both row-major, B accessed by rows = C cols)
// 128x128 tile, BK=8, 256 threads, 8x8 per thread.
// relu!=0: C = relu(C + bias[col])
// ---------------------------------------------------------------------------
__global__ __launch_bounds__(256)
void gemm_nt_kernel(const float* __restrict__ A, const float* __restrict__ Bm,
                    float* __restrict__ C, const float* __restrict__ bias,
                    int M, int N, int K,
                    int strideA, int strideB, int strideC, int relu)
{
    int bz = blockIdx.z;
    A  += (size_t)bz * strideA;
    Bm += (size_t)bz * strideB;
    C  += (size_t)bz * strideC;

    __shared__ __align__(16) float As[8][128];
    __shared__ __align__(16) float Bs[8][128];

    int tid = threadIdx.x;
    int tx = tid & 15;          // 0..15 -> col group
    int ty = tid >> 4;          // 0..15 -> row group
    int rowBase = blockIdx.y * 128;
    int colBase = blockIdx.x * 128;

    int lr = tid >> 1;          // 0..127
    int lc = (tid & 1) * 4;     // 0 or 4

    float acc[8][8];
    #pragma unroll
    for (int i = 0; i < 8; i++)
        #pragma unroll
        for (int j = 0; j < 8; j++) acc[i][j] = 0.f;

    for (int k0 = 0; k0 < K; k0 += 8) {
        float4 a4 = *(const float4*)(A  + (size_t)(rowBase + lr) * K + k0 + lc);
        float4 b4 = *(const float4*)(Bm + (size_t)(colBase + lr) * K + k0 + lc);
        As[lc + 0][lr] = a4.x; As[lc + 1][lr] = a4.y;
        As[lc + 2][lr] = a4.z; As[lc + 3][lr] = a4.w;
        Bs[lc + 0][lr] = b4.x; Bs[lc + 1][lr] = b4.y;
        Bs[lc + 2][lr] = b4.z; Bs[lc + 3][lr] = b4.w;
        __syncthreads();
        #pragma unroll
        for (int k = 0; k < 8; k++) {
            float4 ra0 = *(const float4*)&As[k][ty * 8];
            float4 ra1 = *(const float4*)&As[k][ty * 8 + 4];
            float4 rb0 = *(const float4*)&Bs[k][tx * 8];
            float4 rb1 = *(const float4*)&Bs[k][tx * 8 + 4];
            float ra[8] = {ra0.x, ra0.y, ra0.z, ra0.w, ra1.x, ra1.y, ra1.z, ra1.w};
            float rb[8] = {rb0.x, rb0.y, rb0.z, rb0.w, rb1.x, rb1.y, rb1.z, rb1.w};
            #pragma unroll
            for (int i = 0; i < 8; i++)
                #pragma unroll
                for (int j = 0; j < 8; j++)
                    acc[i][j] += ra[i] * rb[j];
        }
        __syncthreads();
    }

    #pragma unroll
    for (int i = 0; i < 8; i++) {
        int row = rowBase + ty * 8 + i;
        #pragma unroll
        for (int j4 = 0; j4 < 8; j4 += 4) {
            int col = colBase + tx * 8 + j4;
            float4 v;
            v.x = acc[i][j4 + 0]; v.y = acc[i][j4 + 1];
            v.z = acc[i][j4 + 2]; v.w = acc[i][j4 + 3];
            if (relu) {
                v.x = fmaxf(v.x + bias[col + 0], 0.f);
                v.y = fmaxf(v.y + bias[col + 1], 0.f);
                v.z = fmaxf(v.z + bias[col + 2], 0.f);
                v.w = fmaxf(v.w + bias[col + 3], 0.f);
            }
            *(float4*)(C + (size_t)row * N + col) = v;
        }
    }
}

// ---------------------------------------------------------------------------
// Masked softmax over last dim of g_scores[b][i][:]. In place. Masked -> 0.
// ---------------------------------------------------------------------------
__device__ __forceinline__ float warpMax(float v) {
    #pragma unroll
    for (int o = 16; o; o >>= 1) v = fmaxf(v, __shfl_xor_sync(0xffffffffu, v, o));
    return v;
}
__device__ __forceinline__ float warpSum(float v) {
    #pragma unroll
    for (int o = 16; o; o >>= 1) v += __shfl_xor_sync(0xffffffffu, v, o);
    return v;
}

__global__ __launch_bounds__(256)
void softmax_kernel()
{
    int b = blockIdx.y, i = blockIdx.x;
    float* row = g_scores + ((size_t)b * LL + i) * LL;
    const int* mrow = g_x2mask + b * LL;
    int tid = threadIdx.x;

    float v[4]; int mk[4];
    float mx = -3.4e38f;
    #pragma unroll
    for (int t = 0; t < 4; t++) {
        int j = tid + t * 256;
        v[t] = row[j]; mk[t] = mrow[j];
        if (!mk[t]) mx = fmaxf(mx, v[t]);
    }
    __shared__ float redm[8];
    __shared__ float reds[8];
    float wm = warpMax(mx);
    if ((tid & 31) == 0) redm[tid >> 5] = wm;
    __syncthreads();
    if (tid < 32) {
        float t2 = (tid < 8) ? redm[tid] : -3.4e38f;
        t2 = warpMax(t2);
        if (tid == 0) redm[0] = t2;
    }
    __syncthreads();
    mx = redm[0];

    float e[4];
    float s = 0.f;
    #pragma unroll
    for (int t = 0; t < 4; t++) {
        e[t] = mk[t] ? 0.f : __expf(v[t] - mx);
        s += e[t];
    }
    float ws = warpSum(s);
    if ((tid & 31) == 0) reds[tid >> 5] = ws;
    __syncthreads();
    if (tid < 32) {
        float t2 = (tid < 8) ? reds[tid] : 0.f;
        t2 = warpSum(t2);
        if (tid == 0) reds[0] = t2;
    }
    __syncthreads();
    float inv = 1.f / reds[0];
    #pragma unroll
    for (int t = 0; t < 4; t++)
        row[tid + t * 256] = e[t] * inv;
}

// ---------------------------------------------------------------------------
// att = alpha[L,L] @ x2[L,H]  (NN GEMM), epilogue writes concat output:
// out[b,i, 0:H]=x1, [H:2H]=att, [2H:3H]=x1*att, [3H:4H]=x1-att
// ---------------------------------------------------------------------------
__global__ __launch_bounds__(256)
void gemm_nn_concat_kernel(const float* __restrict__ x2,
                           const float* __restrict__ x1,
                           float* __restrict__ out)
{
    int bz = blockIdx.z;
    const float* A  = g_scores + (size_t)bz * LL * LL;      // alpha [L,L]
    const float* Bm = x2 + (size_t)bz * LL * HH;            // [L,H]

    __shared__ __align__(16) float As[8][128];
    __shared__ __align__(16) float Bs[8][128];

    int tid = threadIdx.x;
    int tx = tid & 15;
    int ty = tid >> 4;
    int rowBase = blockIdx.y * 128;     // over L1
    int colBase = blockIdx.x * 128;     // over H

    int lrA = tid >> 1;
    int lcA = (tid & 1) * 4;
    int bk  = tid >> 5;                 // 0..7
    int bn  = (tid & 31) * 4;           // 0..124

    float acc[8][8];
    #pragma unroll
    for (int i = 0; i < 8; i++)
        #pragma unroll
        for (int j = 0; j < 8; j++) acc[i][j] = 0.f;

    for (int k0 = 0; k0 < LL; k0 += 8) {
        float4 a4 = *(const float4*)(A + (size_t)(rowBase + lrA) * LL + k0 + lcA);
        As[lcA + 0][lrA] = a4.x; As[lcA + 1][lrA] = a4.y;
        As[lcA + 2][lrA] = a4.z; As[lcA + 3][lrA] = a4.w;
        float4 b4 = *(const float4*)(Bm + (size_t)(k0 + bk) * HH + colBase + bn);
        *(float4*)&Bs[bk][bn] = b4;
        __syncthreads();
        #pragma unroll
        for (int k = 0; k < 8; k++) {
            float4 ra0 = *(const float4*)&As[k][ty * 8];
            float4 ra1 = *(const float4*)&As[k][ty * 8 + 4];
            float4 rb0 = *(const float4*)&Bs[k][tx * 8];
            float4 rb1 = *(const float4*)&Bs[k][tx * 8 + 4];
            float ra[8] = {ra0.x, ra0.y, ra0.z, ra0.w, ra1.x, ra1.y, ra1.z, ra1.w};
            float rb[8] = {rb0.x, rb0.y, rb0.z, rb0.w, rb1.x, rb1.y, rb1.z, rb1.w};
            #pragma unroll
            for (int i = 0; i < 8; i++)
                #pragma unroll
                for (int j = 0; j < 8; j++)
                    acc[i][j] += ra[i] * rb[j];
        }
        __syncthreads();
    }

    #pragma unroll
    for (int i = 0; i < 8; i++) {
        int row = rowBase + ty * 8 + i;                     // L1 index
        size_t x1base  = ((size_t)bz * LL + row) * HH;
        size_t outbase = ((size_t)bz * LL + row) * (4 * HH);
        #pragma unroll
        for (int j4 = 0; j4 < 8; j4 += 4) {
            int col = colBase + tx * 8 + j4;                // H index
            float4 att;
            att.x = acc[i][j4 + 0]; att.y = acc[i][j4 + 1];
            att.z = acc[i][j4 + 2]; att.w = acc[i][j4 + 3];
            float4 xv = *(const float4*)(x1 + x1base + col);
            float4 prod = {xv.x * att.x, xv.y * att.y, xv.z * att.z, xv.w * att.w};
            float4 diff = {xv.x - att.x, xv.y - att.y, xv.z - att.z, xv.w - att.w};
            *(float4*)(out + outbase + 0 * HH + col) = xv;
            *(float4*)(out + outbase + 1 * HH + col) = att;
            *(float4*)(out + outbase + 2 * HH + col) = prod;
            *(float4*)(out + outbase + 3 * HH + col) = diff;
        }
    }
}

// ---------------------------------------------------------------------------
extern "C" void kernel_launch(void* const* d_in, const int* in_sizes, int n_in,
                              void* d_out, int out_size)
{
    const float* x1  = (const float*)d_in[0];
    const float* x2  = (const float*)d_in[1];
    const unsigned char* x2m = (const unsigned char*)d_in[3];
    const float* W   = (const float*)d_in[4];
    const float* bia = (const float*)d_in[5];
    float* out = (float*)d_out;

    float *xp, *yp, *sc;
    cudaGetSymbolAddress((void**)&xp, g_xproj);
    cudaGetSymbolAddress((void**)&yp, g_yproj);
    cudaGetSymbolAddress((void**)&sc, g_scores);

    // 1) normalize mask dtype
    mask_convert_kernel<<<1, 256>>>(x2m, BB * LL);

    // 2) projections: relu(X @ W^T + b), M = B*L = 16384, N = K = 768
    {
        dim3 grid(HH / 128, (BB * LL) / 128, 1);
        gemm_nt_kernel<<<grid, 256>>>(x1, W, xp, bia,
                                      BB * LL, HH, HH, 0, 0, 0, 1);
        gemm_nt_kernel<<<grid, 256>>>(x2, W, yp, bia,
                                      BB * LL, HH, HH, 0, 0, 0, 1);
    }

    // 3) scores: xp @ yp^T per batch, M=N=1024, K=768
    {
        dim3 grid(LL / 128, LL / 128, BB);
        gemm_nt_kernel<<<grid, 256>>>(xp, yp, sc, nullptr,
                                      LL, LL, HH,
                                      LL * HH, LL * HH, LL * LL, 0);
    }

    // 4) masked softmax in place
    {
        dim3 grid(LL, BB);
        softmax_kernel<<<grid, 256>>>();
    }

    // 5) att = alpha @ x2, fused concat epilogue
    {
        dim3 grid(HH / 128, LL / 128, BB);
        gemm_nn_concat_kernel<<<grid, 256>>>(x2, x1, out);
    }
}

// round 7
// speedup vs baseline: 2.7878x; 2.7878x over previous
#include <cuda_runtime.h>
#include <cuda_bf16.h>
#include <cstdint>

#define BB 16
#define LL 1024
#define HH 768
#define ML (BB*LL)

typedef __nv_bfloat16 bf16;

// ---------------------------------------------------------------------------
// Scratch (device globals — allocation-guard-safe)
// ---------------------------------------------------------------------------
__device__ bf16 g_x1h[ML*HH], g_x1l[ML*HH];
__device__ bf16 g_x2h[ML*HH], g_x2l[ML*HH];
__device__ bf16 g_Wh[HH*HH],  g_Wl[HH*HH];
__device__ bf16 g_xph[ML*HH], g_xpl[ML*HH];
__device__ bf16 g_yph[ML*HH], g_ypl[ML*HH];
__device__ bf16 g_x2Th[(size_t)BB*HH*LL], g_x2Tl[(size_t)BB*HH*LL];
__device__ float g_scores[(size_t)BB*LL*LL];
__device__ bf16 g_ah[(size_t)BB*LL*LL], g_al[(size_t)BB*LL*LL];
__device__ int  g_mask[BB*LL];

// ---------------------------------------------------------------------------
// Helpers (base sm_103 target only: cp.async / ldmatrix / mma.sync — no 'a' features)
// ---------------------------------------------------------------------------
__device__ __forceinline__ uint32_t smem_u32(const void* p) {
    uint32_t a;
    asm("{ .reg .u64 t; cvta.to.shared.u64 t, %1; cvt.u32.u64 %0, t; }" : "=r"(a) : "l"(p));
    return a;
}
__device__ __forceinline__ void cp16(uint32_t s, const void* g) {
    asm volatile("cp.async.cg.shared.global [%0], [%1], 16;" :: "r"(s), "l"(g));
}
#define CP_COMMIT() asm volatile("cp.async.commit_group;" ::: "memory")
template<int N> __device__ __forceinline__ void cp_wait() {
    asm volatile("cp.async.wait_group %0;" :: "n"(N) : "memory");
}
__device__ __forceinline__ void ldm_x4(uint32_t* r, uint32_t addr) {
    asm volatile("ldmatrix.sync.aligned.m8n8.x4.shared.b16 {%0,%1,%2,%3}, [%4];"
                 : "=r"(r[0]), "=r"(r[1]), "=r"(r[2]), "=r"(r[3]) : "r"(addr));
}
__device__ __forceinline__ void lds32(uint32_t& v, uint32_t addr) {
    asm volatile("ld.shared.b32 %0, [%1];" : "=r"(v) : "r"(addr));
}
__device__ __forceinline__ void mma16816(float* d, const uint32_t* a, const uint32_t* b) {
    asm volatile(
        "mma.sync.aligned.m16n8k16.row.col.f32.bf16.bf16.f32 "
        "{%0,%1,%2,%3}, {%4,%5,%6,%7}, {%8,%9}, {%0,%1,%2,%3};"
        : "+f"(d[0]), "+f"(d[1]), "+f"(d[2]), "+f"(d[3])
        : "r"(a[0]), "r"(a[1]), "r"(a[2]), "r"(a[3]), "r"(b[0]), "r"(b[1]));
}

#define SW128(o) ((o) ^ (((o) >> 3) & 0x70))

// Stage layout: Ah 0 | Al 16K | Bh 32K | Bl 48K  (each 128 rows x 64 bf16 = 16KB)
#define STAGE_BYTES 65536
#define SMEM_BYTES  (2 * STAGE_BYTES)

// ---------------------------------------------------------------------------
// bf16x3 warp-MMA GEMM:  D[M,N] = sum_k A[m,k]*B[n,k]  (both K-major rows)
// Tile 128x128, BK=64, 256 threads (8 warps, each 32x64).
// mode 0: relu(D + bias) -> bf16 hi/lo   mode 1: fp32 scores   mode 2: concat
// ---------------------------------------------------------------------------
__global__ __launch_bounds__(256, 1)
void gemm3_kernel(const bf16* __restrict__ Ah, const bf16* __restrict__ Al,
                  const bf16* __restrict__ Bh, const bf16* __restrict__ Bl,
                  int K, int lda, int ldb, size_t strideA, size_t strideB,
                  int mode,
                  float* outF, int ldoF, size_t strideOutF,
                  bf16* outH, bf16* outL, int ldoO,
                  const float* __restrict__ bias,
                  const float* __restrict__ x1, float* __restrict__ outCat)
{
    extern __shared__ char smem[];
    uint32_t sb = smem_u32(smem);
    int tid = threadIdx.x, wid = tid >> 5, lane = tid & 31;
    int bz = blockIdx.z;
    int rowBase = blockIdx.y * 128, colBase = blockIdx.x * 128;

    const bf16* pAh = Ah + strideA * bz + (size_t)rowBase * lda;
    const bf16* pAl = Al + strideA * bz + (size_t)rowBase * lda;
    const bf16* pBh = Bh + strideB * bz + (size_t)colBase * ldb;
    const bf16* pBl = Bl + strideB * bz + (size_t)colBase * ldb;

    int m0 = (wid & 3) * 32, n0 = (wid >> 2) * 64;
    int nChunks = K >> 6;

    float acc[2][8][4];
    #pragma unroll
    for (int mi = 0; mi < 2; mi++)
        #pragma unroll
        for (int ni = 0; ni < 8; ni++)
            #pragma unroll
            for (int q = 0; q < 4; q++) acc[mi][ni][q] = 0.f;

    // ---- async load of one chunk ----
    auto load_chunk = [&](int c) {
        uint32_t st = (uint32_t)(c & 1) * STAGE_BYTES;
        int k0 = c << 6;
        #pragma unroll
        for (int t = 0; t < 4; t++) {
            int v = t * 256 + tid;
            int r = v >> 3, c8 = (v & 7) * 8;
            uint32_t sw = SW128((uint32_t)(r * 128 + c8 * 2));
            size_t goA = (size_t)r * lda + k0 + c8;
            size_t goB = (size_t)r * ldb + k0 + c8;
            cp16(sb + st + sw,         pAh + goA);
            cp16(sb + st + 16384 + sw, pAl + goA);
            cp16(sb + st + 32768 + sw, pBh + goB);
            cp16(sb + st + 49152 + sw, pBl + goB);
        }
    };

    load_chunk(0);
    CP_COMMIT();

    for (int c = 0; c < nChunks; ++c) {
        if (c + 1 < nChunks) {
            load_chunk(c + 1);
            CP_COMMIT();
            cp_wait<1>();
        } else {
            cp_wait<0>();
        }
        __syncthreads();

        uint32_t st = sb + (uint32_t)(c & 1) * STAGE_BYTES;
        #pragma unroll
        for (int ks = 0; ks < 4; ks++) {
            uint32_t ah[2][4], al[2][4];
            #pragma unroll
            for (int mi = 0; mi < 2; mi++) {
                int mat = lane >> 3;
                int r = m0 + mi * 16 + (lane & 7) + (mat & 1) * 8;
                int cc = ks * 16 + (mat >> 1) * 8;
                uint32_t ad = st + SW128((uint32_t)(r * 128 + cc * 2));
                ldm_x4(ah[mi], ad);
                ldm_x4(al[mi], ad + 16384);
            }
            #pragma unroll
            for (int ni = 0; ni < 8; ni++) {
                int n = n0 + ni * 8 + (lane >> 2);
                int k = ks * 16 + (lane & 3) * 2;
                uint32_t o0 = SW128((uint32_t)(n * 128 + k * 2));
                uint32_t o1 = SW128((uint32_t)(n * 128 + (k + 8) * 2));
                uint32_t bh[2], bl[2];
                lds32(bh[0], st + 32768 + o0);
                lds32(bh[1], st + 32768 + o1);
                lds32(bl[0], st + 49152 + o0);
                lds32(bl[1], st + 49152 + o1);
                #pragma unroll
                for (int mi = 0; mi < 2; mi++) {
                    mma16816(acc[mi][ni], ah[mi], bh);
                    mma16816(acc[mi][ni], ah[mi], bl);
                    mma16816(acc[mi][ni], al[mi], bh);
                }
            }
        }
        __syncthreads();
    }

    // ---- epilogue ----
    #pragma unroll
    for (int mi = 0; mi < 2; mi++) {
        #pragma unroll
        for (int ni = 0; ni < 8; ni++) {
            float* d = acc[mi][ni];
            int row0 = rowBase + m0 + mi * 16 + (lane >> 2);
            int row1 = row0 + 8;
            int col  = colBase + n0 + ni * 8 + (lane & 3) * 2;
            if (mode == 0) {
                float2 bb = *(const float2*)(bias + col);
                #pragma unroll
                for (int h = 0; h < 2; h++) {
                    int row = h ? row1 : row0;
                    float f0 = fmaxf(d[2*h + 0] + bb.x, 0.f);
                    float f1 = fmaxf(d[2*h + 1] + bb.y, 0.f);
                    bf16 h0 = __float2bfloat16(f0), h1 = __float2bfloat16(f1);
                    bf16 g0 = __float2bfloat16(f0 - __bfloat162float(h0));
                    bf16 g1 = __float2bfloat16(f1 - __bfloat162float(h1));
                    uint32_t hv = (uint32_t)__bfloat16_as_ushort(h0) | ((uint32_t)__bfloat16_as_ushort(h1) << 16);
                    uint32_t lv = (uint32_t)__bfloat16_as_ushort(g0) | ((uint32_t)__bfloat16_as_ushort(g1) << 16);
                    *(uint32_t*)(outH + (size_t)row * ldoO + col) = hv;
                    *(uint32_t*)(outL + (size_t)row * ldoO + col) = lv;
                }
            } else if (mode == 1) {
                float* of = outF + strideOutF * bz;
                *(float2*)(of + (size_t)row0 * ldoF + col) = make_float2(d[0], d[1]);
                *(float2*)(of + (size_t)row1 * ldoF + col) = make_float2(d[2], d[3]);
            } else {
                #pragma unroll
                for (int h = 0; h < 2; h++) {
                    int row = h ? row1 : row0;
                    size_t rw = (size_t)bz * LL + row;
                    float2 xv = *(const float2*)(x1 + rw * HH + col);
                    float2 av = make_float2(d[2*h], d[2*h + 1]);
                    float* ob = outCat + rw * (4 * HH) + col;
                    *(float2*)(ob         ) = xv;
                    *(float2*)(ob +     HH) = av;
                    *(float2*)(ob + 2 * HH) = make_float2(xv.x * av.x, xv.y * av.y);
                    *(float2*)(ob + 3 * HH) = make_float2(xv.x - av.x, xv.y - av.y);
                }
            }
        }
    }
}

// ---------------------------------------------------------------------------
// fp32 -> bf16 hi/lo split
// ---------------------------------------------------------------------------
__global__ void split_kernel(const float* __restrict__ in, bf16* __restrict__ h,
                             bf16* __restrict__ l, int n4)
{
    int i = blockIdx.x * blockDim.x + threadIdx.x;
    if (i >= n4) return;
    float4 v = ((const float4*)in)[i];
    bf16 h0 = __float2bfloat16(v.x), h1 = __float2bfloat16(v.y);
    bf16 h2 = __float2bfloat16(v.z), h3 = __float2bfloat16(v.w);
    bf16 l0 = __float2bfloat16(v.x - __bfloat162float(h0));
    bf16 l1 = __float2bfloat16(v.y - __bfloat162float(h1));
    bf16 l2 = __float2bfloat16(v.z - __bfloat162float(h2));
    bf16 l3 = __float2bfloat16(v.w - __bfloat162float(h3));
    uint2 hv, lv;
    hv.x = (uint32_t)__bfloat16_as_ushort(h0) | ((uint32_t)__bfloat16_as_ushort(h1) << 16);
    hv.y = (uint32_t)__bfloat16_as_ushort(h2) | ((uint32_t)__bfloat16_as_ushort(h3) << 16);
    lv.x = (uint32_t)__bfloat16_as_ushort(l0) | ((uint32_t)__bfloat16_as_ushort(l1) << 16);
    lv.y = (uint32_t)__bfloat16_as_ushort(l2) | ((uint32_t)__bfloat16_as_ushort(l3) << 16);
    ((uint2*)h)[i] = hv;
    ((uint2*)l)[i] = lv;
}

// ---------------------------------------------------------------------------
// x2[b][j][d] -> x2T[b][d][j] bf16 hi/lo
// ---------------------------------------------------------------------------
__global__ void transpose_split_kernel(const float* __restrict__ x2)
{
    __shared__ float tile[32][33];
    int b = blockIdx.z;
    int j0 = blockIdx.x * 32, d0 = blockIdx.y * 32;
    int tx = threadIdx.x, ty = threadIdx.y;       // 32 x 8
    const float* src = x2 + ((size_t)b * LL + j0) * HH + d0;
    #pragma unroll
    for (int t = 0; t < 4; t++) {
        int j = ty + t * 8;
        tile[j][tx] = src[(size_t)j * HH + tx];
    }
    __syncthreads();
    bf16* dh = g_x2Th + ((size_t)b * HH + d0) * LL + j0;
    bf16* dl = g_x2Tl + ((size_t)b * HH + d0) * LL + j0;
    #pragma unroll
    for (int t = 0; t < 4; t++) {
        int d = ty + t * 8;
        float v = tile[tx][d];
        bf16 h = __float2bfloat16(v);
        bf16 l = __float2bfloat16(v - __bfloat162float(h));
        dh[(size_t)d * LL + tx] = h;
        dl[(size_t)d * LL + tx] = l;
    }
}

// ---------------------------------------------------------------------------
// Mask dtype detection + normalization
// ---------------------------------------------------------------------------
__global__ void mask_convert_kernel(const unsigned char* __restrict__ m, int n) {
    __shared__ int s0_sh, s123_sh;
    int tid = threadIdx.x;
    if (tid == 0) { s0_sh = 0; s123_sh = 0; }
    __syncthreads();
    int o0 = 0, o123 = 0;
    for (int i = tid; i < n; i += blockDim.x) {
        unsigned char v = m[i];
        if ((i & 3) == 0) o0 |= v; else o123 |= v;
    }
    atomicOr(&s0_sh, o0);
    atomicOr(&s123_sh, o123);
    __syncthreads();
    int mode;
    if (s123_sh == 0)      mode = 1;   // int32
    else if (s0_sh == 0)   mode = 2;   // float32
    else                   mode = 0;   // uint8
    for (int j = tid; j < n; j += blockDim.x) {
        int v;
        if (mode == 1)      v = (m[4 * j] != 0);
        else if (mode == 2) v = ((m[4 * j + 1] | m[4 * j + 2] | m[4 * j + 3]) != 0);
        else                v = (m[j] != 0);
        g_mask[j] = v;
    }
}

// ---------------------------------------------------------------------------
// Masked softmax over scores rows -> alpha bf16 hi/lo
// ---------------------------------------------------------------------------
__device__ __forceinline__ float warpMax(float v) {
    #pragma unroll
    for (int o = 16; o; o >>= 1) v = fmaxf(v, __shfl_xor_sync(0xffffffffu, v, o));
    return v;
}
__device__ __forceinline__ float warpSum(float v) {
    #pragma unroll
    for (int o = 16; o; o >>= 1) v += __shfl_xor_sync(0xffffffffu, v, o);
    return v;
}

__global__ __launch_bounds__(256)
void softmax_kernel()
{
    int b = blockIdx.y, i = blockIdx.x;
    const float* row = g_scores + ((size_t)b * LL + i) * LL;
    const int* mrow = g_mask + b * LL;
    bf16* ah = g_ah + ((size_t)b * LL + i) * LL;
    bf16* al = g_al + ((size_t)b * LL + i) * LL;
    int tid = threadIdx.x;

    float v[4]; int mk[4];
    float mx = -3.4e38f;
    #pragma unroll
    for (int t = 0; t < 4; t++) {
        int j = tid + t * 256;
        v[t] = row[j]; mk[t] = mrow[j];
        if (!mk[t]) mx = fmaxf(mx, v[t]);
    }
    __shared__ float redm[8], reds[8];
    float wm = warpMax(mx);
    if ((tid & 31) == 0) redm[tid >> 5] = wm;
    __syncthreads();
    if (tid < 32) {
        float t2 = (tid < 8) ? redm[tid] : -3.4e38f;
        t2 = warpMax(t2);
        if (tid == 0) redm[0] = t2;
    }
    __syncthreads();
    mx = redm[0];

    float e[4], s = 0.f;
    #pragma unroll
    for (int t = 0; t < 4; t++) {
        e[t] = mk[t] ? 0.f : __expf(v[t] - mx);
        s += e[t];
    }
    float ws = warpSum(s);
    if ((tid & 31) == 0) reds[tid >> 5] = ws;
    __syncthreads();
    if (tid < 32) {
        float t2 = (tid < 8) ? reds[tid] : 0.f;
        t2 = warpSum(t2);
        if (tid == 0) reds[0] = t2;
    }
    __syncthreads();
    float inv = 1.f / reds[0];
    #pragma unroll
    for (int t = 0; t < 4; t++) {
        int j = tid + t * 256;
        float a = e[t] * inv;
        bf16 h = __float2bfloat16(a);
        bf16 l = __float2bfloat16(a - __bfloat162float(h));
        ah[j] = h; al[j] = l;
    }
}

// ---------------------------------------------------------------------------
extern "C" void kernel_launch(void* const* d_in, const int* in_sizes, int n_in,
                              void* d_out, int out_size)
{
    const float* x1  = (const float*)d_in[0];
    const float* x2  = (const float*)d_in[1];
    const unsigned char* x2m = (const unsigned char*)d_in[3];
    const float* W   = (const float*)d_in[4];
    const float* bia = (const float*)d_in[5];
    float* out = (float*)d_out;

    cudaFuncSetAttribute(gemm3_kernel, cudaFuncAttributeMaxDynamicSharedMemorySize, SMEM_BYTES);

    bf16 *x1h, *x1l, *x2h, *x2l, *Wh, *Wl, *xph, *xpl, *yph, *ypl, *x2Th, *x2Tl, *ah, *al;
    float* sc;
    cudaGetSymbolAddress((void**)&x1h, g_x1h); cudaGetSymbolAddress((void**)&x1l, g_x1l);
    cudaGetSymbolAddress((void**)&x2h, g_x2h); cudaGetSymbolAddress((void**)&x2l, g_x2l);
    cudaGetSymbolAddress((void**)&Wh,  g_Wh);  cudaGetSymbolAddress((void**)&Wl,  g_Wl);
    cudaGetSymbolAddress((void**)&xph, g_xph); cudaGetSymbolAddress((void**)&xpl, g_xpl);
    cudaGetSymbolAddress((void**)&yph, g_yph); cudaGetSymbolAddress((void**)&ypl, g_ypl);
    cudaGetSymbolAddress((void**)&x2Th, g_x2Th); cudaGetSymbolAddress((void**)&x2Tl, g_x2Tl);
    cudaGetSymbolAddress((void**)&ah,  g_ah);  cudaGetSymbolAddress((void**)&al,  g_al);
    cudaGetSymbolAddress((void**)&sc,  g_scores);

    // 1) mask
    mask_convert_kernel<<<1, 256>>>(x2m, BB * LL);

    // 2) splits
    {
        int n4 = ML * HH / 4;
        split_kernel<<<(n4 + 255) / 256, 256>>>(x1, x1h, x1l, n4);
        split_kernel<<<(n4 + 255) / 256, 256>>>(x2, x2h, x2l, n4);
        int w4 = HH * HH / 4;
        split_kernel<<<(w4 + 255) / 256, 256>>>(W, Wh, Wl, w4);
    }
    // 3) transpose-split x2
    {
        dim3 grid(LL / 32, HH / 32, BB);
        transpose_split_kernel<<<grid, dim3(32, 8)>>>(x2);
    }
    // 4) projections (mode 0): relu(X @ W^T + b) -> bf16 hi/lo
    {
        dim3 grid(HH / 128, ML / 128, 1);
        gemm3_kernel<<<grid, 256, SMEM_BYTES>>>(x1h, x1l, Wh, Wl, HH, HH, HH, 0, 0,
                                                0, nullptr, 0, 0, xph, xpl, HH, bia, nullptr, nullptr);
        gemm3_kernel<<<grid, 256, SMEM_BYTES>>>(x2h, x2l, Wh, Wl, HH, HH, HH, 0, 0,
                                                0, nullptr, 0, 0, yph, ypl, HH, bia, nullptr, nullptr);
    }
    // 5) scores (mode 1): xp @ yp^T
    {
        dim3 grid(LL / 128, LL / 128, BB);
        gemm3_kernel<<<grid, 256, SMEM_BYTES>>>(xph, xpl, yph, ypl, HH, HH, HH,
                                                (size_t)LL * HH, (size_t)LL * HH,
                                                1, sc, LL, (size_t)LL * LL,
                                                nullptr, nullptr, 0, nullptr, nullptr, nullptr);
    }
    // 6) masked softmax -> alpha bf16 hi/lo
    {
        dim3 grid(LL, BB);
        softmax_kernel<<<grid, 256>>>();
    }
    // 7) att (mode 2): alpha @ x2 with concat epilogue
    {
        dim3 grid(HH / 128, LL / 128, BB);
        gemm3_kernel<<<grid, 256, SMEM_BYTES>>>(ah, al, x2Th, x2Tl, LL, LL, LL,
                                                (size_t)LL * LL, (size_t)HH * LL,
                                                2, nullptr, 0, 0,
                                                nullptr, nullptr, 0, nullptr, x1, out);
    }
}